// round 4
// baseline (speedup 1.0000x reference)
#include <cuda_runtime.h>
#include <cstdint>

// Problem constants
#define T_STEPS 512
#define BATCH   32
#define DIM     512
#define HID     256
#define A1N     16
#define A2N     128

typedef unsigned long long ull;

// ---------------- device scratch (allocation-free rule: __device__ globals) ----
__device__ float g_lut[8200];                    // exp(f(x)) lookup table
__device__ float g_seq[T_STEPS * BATCH];         // stage-1 output (T,B)
__device__ float g_hs [T_STEPS * BATCH * HID];   // LSTM hidden history (T,B,H)
__device__ float g_s2 [T_STEPS * BATCH];         // stage-3 logits (T,B)

// =============================================================================
// K0: build LUT  g(x) = exp( sum_a u1[a] * tanh(x*W1[a] + b1[a]) ),  x in [-8,8]
// =============================================================================
__global__ void k0_lut(const float* __restrict__ W1,
                       const float* __restrict__ b1,
                       const float* __restrict__ u1) {
    int i = blockIdx.x * blockDim.x + threadIdx.x;
    if (i > 8192) return;
    float x = -8.f + (float)i * (16.f / 8192.f);
    float f = 0.f;
#pragma unroll
    for (int a = 0; a < A1N; a++)
        f += u1[a] * tanhf(x * W1[a] + b1[a]);
    g_lut[i] = expf(f);
}

// =============================================================================
// K1: AttLayer1 soft pool over D.  seq[t,b] = sum_d x*g(x) / sum_d g(x)
// =============================================================================
__global__ __launch_bounds__(256) void k1_att1(const float* __restrict__ x) {
    __shared__ float lut[8193];
    for (int i = threadIdx.x; i < 8193; i += 256) lut[i] = g_lut[i];
    __syncthreads();

    int warp = threadIdx.x >> 5, lane = threadIdx.x & 31;
#pragma unroll
    for (int q = 0; q < 4; q++) {
        int pair = blockIdx.x * 32 + warp * 4 + q;     // pair = t*B + b
        const float* xp = x + (size_t)pair * DIM;
        float aw = 0.f, axw = 0.f;
#pragma unroll 4
        for (int d = lane; d < DIM; d += 32) {
            float v = xp[d];
            float pos = (v + 8.f) * 512.f;             // 8192/16 per unit x
            pos = fminf(fmaxf(pos, 0.f), 8191.0f);
            int   i0 = (int)pos;
            float fr = pos - (float)i0;
            float g0 = lut[i0], g1 = lut[i0 + 1];
            float g  = g0 + fr * (g1 - g0);
            aw  += g;
            axw += v * g;
        }
#pragma unroll
        for (int o = 16; o > 0; o >>= 1) {
            aw  += __shfl_xor_sync(0xFFFFFFFFu, aw,  o);
            axw += __shfl_xor_sync(0xFFFFFFFFu, axw, o);
        }
        if (lane == 0) g_seq[pair] = axw / aw;
    }
}

// =============================================================================
// K2: LSTM recurrence.  16 clusters x 8 CTAs. Cluster c owns batches 2c, 2c+1.
// CTA rank r owns h-units [32r, 32r+32) -> 128 gate rows (4 gates x 32 units).
// Thread (rg = tid>>4, kg = tid&15): 8 rows x 16 k x 2 batches.
// Weights register-resident; each h float4 loaded ONCE serves 8 rows.
// Partial sums reduced across 16 lanes via butterfly shfl.
// h exchange: publish to own smem -> cluster.sync -> gather via mapa/ld.
// =============================================================================
__device__ __forceinline__ unsigned smem_u32(const void* p) {
    unsigned a;
    asm("{ .reg .u64 t; cvta.to.shared.u64 t, %1; cvt.u32.u64 %0, t; }"
        : "=r"(a) : "l"(p));
    return a;
}

__global__ void __cluster_dims__(8, 1, 1) __launch_bounds__(256, 1)
k2_lstm(const float* __restrict__ Whh, const float* __restrict__ Wih,
        const float* __restrict__ bih, const float* __restrict__ bhh,
        const float* __restrict__ h0,  const float* __restrict__ c0) {
    // hbuf[ph][p] = {b0[2p], b0[2p+1], b1[2p], b1[2p+1]}  (gathered, full H)
    __shared__ float4 hbuf[2][128];
    __shared__ float  hpub[2][2][32];    // this CTA's published h: [ph][batch][unit]
    __shared__ float  gates[128][2];     // reduced gate pre-activations
    __shared__ float  sq[2][T_STEPS];    // seq for the 2 batches

    const int tid = threadIdx.x;
    unsigned rank;
    asm("mov.u32 %0, %%cluster_ctarank;" : "=r"(rank));
    const int cid = blockIdx.x >> 3;
    const int b0g = cid * 2;

    const int rg = tid >> 4;    // row group: rows rg*8 .. rg*8+7 (of 128)
    const int kg = tid & 15;    // k group:   k    kg*16 .. kg*16+15

    // ---- register-resident weights: 8 rows x 8 f32x2-pairs (128 floats) ------
    ull w[8][8];
#pragma unroll
    for (int i = 0; i < 8; i++) {
        int l = rg * 8 + i;                                  // local gate row
        int grow = (l >> 5) * HID + (int)rank * 32 + (l & 31);
        const ull* wrow = reinterpret_cast<const ull*>(Whh)
                          + (size_t)grow * 128 + kg * 8;
#pragma unroll
        for (int j = 0; j < 8; j++) w[i][j] = wrow[j];
    }

    // ---- updater state/consts: threads 0..63 own (batch=tid>>5, unit=tid&31) -
    const int ub = tid >> 5, uu = tid & 31;
    float creg = 0.f, bs[4], wi[4];
    if (tid < 64) {
        creg = c0[(b0g + ub) * HID + (int)rank * 32 + uu];
#pragma unroll
        for (int g = 0; g < 4; g++) {
            int grow = g * HID + (int)rank * 32 + uu;
            bs[g] = bih[grow] + bhh[grow];
            wi[g] = Wih[grow];
        }
    }

    // ---- preload seq (both batches) ------------------------------------------
    for (int i = tid; i < 2 * T_STEPS; i += 256) {
        int bb = i >> 9, tt = i & 511;
        sq[bb][tt] = g_seq[tt * BATCH + b0g + bb];
    }
    // ---- fill hbuf[0] locally from h0 ----------------------------------------
    for (int i = tid; i < 2 * HID; i += 256) {
        int bb = i >> 8, U = i & 255;
        ((float*)&hbuf[0][U >> 1])[(U & 1) + 2 * bb] = h0[(b0g + bb) * HID + U];
    }
    __syncthreads();

    const unsigned hpub_base = smem_u32(&hpub[0][0][0]);
    // gather plan: this thread fetches unit U=tid for both batches
    const unsigned gU = (unsigned)tid;        // 0..255
    const unsigned grank = gU >> 5;           // source CTA rank

    for (int t = 0; t < T_STEPS; t++) {
        const int ph = t & 1, nph = ph ^ 1;

        // ---- GEMV fragment: 8 rows x 16 k x 2 batches -------------------------
        const ulonglong2* hp =
            reinterpret_cast<const ulonglong2*>(&hbuf[ph][kg * 8]);
        ull acc0[8], acc1[8];
#pragma unroll
        for (int i = 0; i < 8; i++) { acc0[i] = 0ULL; acc1[i] = 0ULL; }
#pragma unroll
        for (int j = 0; j < 8; j++) {
            ulonglong2 h2 = hp[j];      // .x = batch0 k-pair, .y = batch1 k-pair
#pragma unroll
            for (int i = 0; i < 8; i++) {
                asm("fma.rn.f32x2 %0, %1, %2, %0;" : "+l"(acc0[i]) : "l"(w[i][j]), "l"(h2.x));
                asm("fma.rn.f32x2 %0, %1, %2, %0;" : "+l"(acc1[i]) : "l"(w[i][j]), "l"(h2.y));
            }
        }
        // collapse f32x2 lanes:  v[2i+b] = partial sum for (row rg*8+i, batch b)
        float v[16];
#pragma unroll
        for (int i = 0; i < 8; i++) {
            float lo, hi;
            asm("mov.b64 {%0,%1}, %2;" : "=f"(lo), "=f"(hi) : "l"(acc0[i]));
            v[2 * i] = lo + hi;
            asm("mov.b64 {%0,%1}, %2;" : "=f"(lo), "=f"(hi) : "l"(acc1[i]));
            v[2 * i + 1] = lo + hi;
        }

        // ---- butterfly reduce across 16 lanes; lane kg ends with value m=kg --
        {
            bool hi8 = (kg & 8) != 0;
#pragma unroll
            for (int m = 0; m < 8; m++) {
                float send = hi8 ? v[m] : v[m + 8];
                float recv = __shfl_xor_sync(0xFFFFFFFFu, send, 8);
                v[m] = (hi8 ? v[m + 8] : v[m]) + recv;
            }
            bool hi4 = (kg & 4) != 0;
#pragma unroll
            for (int m = 0; m < 4; m++) {
                float send = hi4 ? v[m] : v[m + 4];
                float recv = __shfl_xor_sync(0xFFFFFFFFu, send, 4);
                v[m] = (hi4 ? v[m + 4] : v[m]) + recv;
            }
            bool hi2 = (kg & 2) != 0;
#pragma unroll
            for (int m = 0; m < 2; m++) {
                float send = hi2 ? v[m] : v[m + 2];
                float recv = __shfl_xor_sync(0xFFFFFFFFu, send, 2);
                v[m] = (hi2 ? v[m + 2] : v[m]) + recv;
            }
            bool hi1 = (kg & 1) != 0;
            {
                float send = hi1 ? v[0] : v[1];
                float recv = __shfl_xor_sync(0xFFFFFFFFu, send, 1);
                v[0] = (hi1 ? v[1] : v[0]) + recv;
            }
        }
        gates[rg * 8 + (kg >> 1)][kg & 1] = v[0];
        __syncthreads();

        // ---- state update (64 threads); publish to OWN smem -------------------
        if (tid < 64) {
            float xt = sq[ub][t];
            float gi = gates[uu][ub]      + bs[0] + wi[0] * xt;
            float gf = gates[32 + uu][ub] + bs[1] + wi[1] * xt;
            float gg = gates[64 + uu][ub] + bs[2] + wi[2] * xt;
            float go = gates[96 + uu][ub] + bs[3] + wi[3] * xt;
            float ci = 1.f / (1.f + expf(-gi));
            float cf = 1.f / (1.f + expf(-gf));
            float co = 1.f / (1.f + expf(-go));
            creg = cf * creg + ci * tanhf(gg);
            float hv = co * tanhf(creg);

            hpub[nph][ub][uu] = hv;
            g_hs[((size_t)t * BATCH + b0g + ub) * HID + (int)rank * 32 + uu] = hv;
        }

        // ---- cluster barrier: release own hpub writes, acquire peers' ---------
        asm volatile("barrier.cluster.arrive.aligned;" ::: "memory");
        asm volatile("barrier.cluster.wait.aligned;"   ::: "memory");

        // ---- gather full h (2 batches, unit U=tid) into hbuf[nph] -------------
        {
            unsigned la0 = hpub_base + (unsigned)((nph * 64 + 0 * 32 + (gU & 31)) * 4);
            unsigned la1 = hpub_base + (unsigned)((nph * 64 + 1 * 32 + (gU & 31)) * 4);
            unsigned ra0, ra1;
            asm("mapa.shared::cluster.u32 %0, %1, %2;" : "=r"(ra0) : "r"(la0), "r"(grank));
            asm("mapa.shared::cluster.u32 %0, %1, %2;" : "=r"(ra1) : "r"(la1), "r"(grank));
            float v0, v1;
            asm volatile("ld.shared::cluster.f32 %0, [%1];" : "=f"(v0) : "r"(ra0));
            asm volatile("ld.shared::cluster.f32 %0, [%1];" : "=f"(v1) : "r"(ra1));
            ((float*)&hbuf[nph][gU >> 1])[(gU & 1) + 0] = v0;   // batch 0
            ((float*)&hbuf[nph][gU >> 1])[(gU & 1) + 2] = v1;   // batch 1
        }
        __syncthreads();   // hbuf[nph] ready for next step
    }

    // keep smem alive until all peers finished their final gather
    asm volatile("barrier.cluster.arrive.aligned;" ::: "memory");
    asm volatile("barrier.cluster.wait.aligned;"   ::: "memory");
}

// =============================================================================
// K3: AttLayer2 logits.  s2[t,b] = sum_a u2[a]*tanh( hs[t,b,:]@W2[:,a] + b2[a] )
// 128 CTAs: (b, t-quarter). 8x8 register tiles, f32x2.
// =============================================================================
__global__ __launch_bounds__(256) void k3_att2(const float* __restrict__ W2,
                                               const float* __restrict__ b2,
                                               const float* __restrict__ u2) {
    __shared__ float sh[128][33];   // [t-local][k]  (padded)
    __shared__ float sw[32][128];   // [k][a]
    __shared__ float sp[128][17];   // partial [t-local][tx]
    __shared__ float sb2[A2N], su2[A2N];

    const int tid = threadIdx.x;
    const int b = blockIdx.x & 31, tq = blockIdx.x >> 5;
    const int t0 = tq * 128;
    if (tid < A2N) { sb2[tid] = b2[tid]; su2[tid] = u2[tid]; }

    const int tx = tid & 15;   // a-group (8 a's each)
    const int ty = tid >> 4;   // t-group (8 t's each)

    ull acc[8][4];
#pragma unroll
    for (int i = 0; i < 8; i++)
#pragma unroll
        for (int p = 0; p < 4; p++) acc[i][p] = 0ULL;

    for (int kc = 0; kc < 8; kc++) {
        __syncthreads();
        for (int idx = tid; idx < 4096; idx += 256) {
            int tl = idx >> 5, k = idx & 31;
            sh[tl][k] = g_hs[((size_t)(t0 + tl) * BATCH + b) * HID + kc * 32 + k];
        }
        for (int idx = tid; idx < 4096; idx += 256) {
            int k = idx >> 7, a = idx & 127;
            sw[k][a] = W2[(kc * 32 + k) * A2N + a];
        }
        __syncthreads();
#pragma unroll 4
        for (int k = 0; k < 32; k++) {
            const ull* wv = reinterpret_cast<const ull*>(&sw[k][tx * 8]);
            ull w0 = wv[0], w1 = wv[1], w2_ = wv[2], w3 = wv[3];
#pragma unroll
            for (int i = 0; i < 8; i++) {
                float hvv = sh[ty * 8 + i][k];
                ull hh;
                asm("mov.b64 %0, {%1,%1};" : "=l"(hh) : "f"(hvv));
                asm("fma.rn.f32x2 %0, %1, %2, %0;" : "+l"(acc[i][0]) : "l"(w0),  "l"(hh));
                asm("fma.rn.f32x2 %0, %1, %2, %0;" : "+l"(acc[i][1]) : "l"(w1),  "l"(hh));
                asm("fma.rn.f32x2 %0, %1, %2, %0;" : "+l"(acc[i][2]) : "l"(w2_), "l"(hh));
                asm("fma.rn.f32x2 %0, %1, %2, %0;" : "+l"(acc[i][3]) : "l"(w3),  "l"(hh));
            }
        }
    }
    // epilogue: tanh + u2 dot over this thread's 8 a's
    float sres[8];
#pragma unroll
    for (int i = 0; i < 8; i++) sres[i] = 0.f;
#pragma unroll
    for (int i = 0; i < 8; i++) {
#pragma unroll
        for (int p = 0; p < 4; p++) {
            float lo, hi;
            asm("mov.b64 {%0,%1}, %2;" : "=f"(lo), "=f"(hi) : "l"(acc[i][p]));
            int a0 = tx * 8 + p * 2;
            sres[i] += su2[a0]     * tanhf(lo + sb2[a0]);
            sres[i] += su2[a0 + 1] * tanhf(hi + sb2[a0 + 1]);
        }
    }
#pragma unroll
    for (int i = 0; i < 8; i++) sp[ty * 8 + i][tx] = sres[i];
    __syncthreads();
    if (tid < 128) {
        float s = 0.f;
#pragma unroll
        for (int xx = 0; xx < 16; xx++) s += sp[tid][xx];
        g_s2[(t0 + tid) * BATCH + b] = s;
    }
}

// =============================================================================
// K4: softmax over T, attention pool, linear head.  One CTA per batch.
// =============================================================================
__global__ __launch_bounds__(256) void k4_final(const float* __restrict__ Wl,
                                                const float* __restrict__ bl,
                                                float* __restrict__ out) {
    __shared__ float a2s[T_STEPS];
    __shared__ float red[256];
    const int b = blockIdx.x, tid = threadIdx.x;

    for (int t = tid; t < T_STEPS; t += 256)
        a2s[t] = expf(g_s2[t * BATCH + b]);
    __syncthreads();

    float p = a2s[tid] + a2s[tid + 256];
    red[tid] = p;
    __syncthreads();
#pragma unroll
    for (int o = 128; o > 0; o >>= 1) {
        if (tid < o) red[tid] += red[tid + o];
        __syncthreads();
    }
    const float inv = 1.f / red[0];
    __syncthreads();

    // pooled[u] = sum_t a2[t] * hs[t][b][u]   (tid = u)
    float acc = 0.f;
    const float* hp = g_hs + (size_t)b * HID + tid;
#pragma unroll 8
    for (int t = 0; t < T_STEPS; t++)
        acc += a2s[t] * hp[(size_t)t * BATCH * HID];
    acc *= inv;

    float v = acc * Wl[tid];
    red[tid] = v;
    __syncthreads();
#pragma unroll
    for (int o = 128; o > 0; o >>= 1) {
        if (tid < o) red[tid] += red[tid + o];
        __syncthreads();
    }
    if (tid == 0) out[b] = red[0] + bl[0];
}

// =============================================================================
// launcher
// =============================================================================
extern "C" void kernel_launch(void* const* d_in, const int* in_sizes, int n_in,
                              void* d_out, int out_size) {
    const float* inputs = (const float*)d_in[0];
    const float* W1  = (const float*)d_in[1];
    const float* b1  = (const float*)d_in[2];
    const float* u1  = (const float*)d_in[3];
    const float* Wih = (const float*)d_in[4];
    const float* Whh = (const float*)d_in[5];
    const float* bih = (const float*)d_in[6];
    const float* bhh = (const float*)d_in[7];
    const float* h0  = (const float*)d_in[8];
    const float* c0  = (const float*)d_in[9];
    const float* W2  = (const float*)d_in[10];
    const float* b2  = (const float*)d_in[11];
    const float* u2  = (const float*)d_in[12];
    const float* Wl  = (const float*)d_in[13];
    const float* bl  = (const float*)d_in[14];
    float* out = (float*)d_out;

    k0_lut  <<<33, 256>>>(W1, b1, u1);
    k1_att1 <<<512, 256>>>(inputs);
    k2_lstm <<<128, 256>>>(Whh, Wih, bih, bhh, h0, c0);
    k3_att2 <<<128, 256>>>(W2, b2, u2);
    k4_final<<<32, 256>>>(Wl, bl, out);
}

// round 5
// speedup vs baseline: 1.3525x; 1.3525x over previous
#include <cuda_runtime.h>
#include <cstdint>

// Problem constants
#define T_STEPS 512
#define BATCH   32
#define DIM     512
#define HID     256
#define A1N     16
#define A2N     128

typedef unsigned long long ull;

// ---------------- device scratch (allocation-free rule: __device__ globals) ----
__device__ float g_lut[8200];                    // exp(f(x)) lookup table
__device__ float g_seq[T_STEPS * BATCH];         // stage-1 output (T,B)
__device__ float g_hs [T_STEPS * BATCH * HID];   // LSTM hidden history (T,B,H)
__device__ float g_s2 [T_STEPS * BATCH];         // stage-3 logits (T,B)

// =============================================================================
// K0: build LUT  g(x) = exp( sum_a u1[a] * tanh(x*W1[a] + b1[a]) ),  x in [-8,8]
// =============================================================================
__global__ void k0_lut(const float* __restrict__ W1,
                       const float* __restrict__ b1,
                       const float* __restrict__ u1) {
    int i = blockIdx.x * blockDim.x + threadIdx.x;
    if (i > 8192) return;
    float x = -8.f + (float)i * (16.f / 8192.f);
    float f = 0.f;
#pragma unroll
    for (int a = 0; a < A1N; a++)
        f += u1[a] * tanhf(x * W1[a] + b1[a]);
    g_lut[i] = expf(f);
}

// =============================================================================
// K1: AttLayer1 soft pool over D.  seq[t,b] = sum_d x*g(x) / sum_d g(x)
// =============================================================================
__global__ __launch_bounds__(256) void k1_att1(const float* __restrict__ x) {
    __shared__ float lut[8193];
    for (int i = threadIdx.x; i < 8193; i += 256) lut[i] = g_lut[i];
    __syncthreads();

    int warp = threadIdx.x >> 5, lane = threadIdx.x & 31;
#pragma unroll
    for (int q = 0; q < 4; q++) {
        int pair = blockIdx.x * 32 + warp * 4 + q;     // pair = t*B + b
        const float* xp = x + (size_t)pair * DIM;
        float aw = 0.f, axw = 0.f;
#pragma unroll 4
        for (int d = lane; d < DIM; d += 32) {
            float v = xp[d];
            float pos = (v + 8.f) * 512.f;             // 8192/16 per unit x
            pos = fminf(fmaxf(pos, 0.f), 8191.0f);
            int   i0 = (int)pos;
            float fr = pos - (float)i0;
            float g0 = lut[i0], g1 = lut[i0 + 1];
            float g  = g0 + fr * (g1 - g0);
            aw  += g;
            axw += v * g;
        }
#pragma unroll
        for (int o = 16; o > 0; o >>= 1) {
            aw  += __shfl_xor_sync(0xFFFFFFFFu, aw,  o);
            axw += __shfl_xor_sync(0xFFFFFFFFu, axw, o);
        }
        if (lane == 0) g_seq[pair] = axw / aw;
    }
}

// =============================================================================
// K_NOP: profiling-slot alignment dummy (shifts ncu's fixed capture slot onto k2)
// =============================================================================
__global__ void k_nop() {}

// =============================================================================
// K2: LSTM recurrence.  16 clusters x 8 CTAs. Cluster c owns batches 2c, 2c+1.
// CTA rank r owns h-units [32r, 32r+32) -> 128 gate rows (4 gates x 32 units).
// Thread layout (R2-proven): l = tid&127 (gate row), kh = tid>>7 (k half).
// Weights register-resident (128 regs); mainloop LDS is pure broadcast.
// Exchange: updaters PUSH h to all 8 CTAs' hbuf (st.shared::cluster), then
// remote mbarrier arrive; consumers try_wait + read LOCAL smem.
// =============================================================================
__device__ __forceinline__ unsigned smem_u32(const void* p) {
    unsigned a;
    asm("{ .reg .u64 t; cvta.to.shared.u64 t, %1; cvt.u32.u64 %0, t; }"
        : "=r"(a) : "l"(p));
    return a;
}

__device__ __forceinline__ void mbar_wait_acq(unsigned addr, int parity) {
    asm volatile(
        "{\n\t.reg .pred P;\n\t"
        "WAITL_%=:\n\t"
        "mbarrier.try_wait.parity.acquire.cluster.shared::cta.b64 P, [%0], %1, 0x989680;\n\t"
        "@P bra.uni WAITD_%=;\n\t"
        "bra.uni WAITL_%=;\n\t"
        "WAITD_%=:\n\t}"
        :: "r"(addr), "r"(parity) : "memory");
}

__device__ __forceinline__ float fsigmoid(float x) {
    return __fdividef(1.f, 1.f + __expf(-x));
}
__device__ __forceinline__ float ftanh(float x) {
    return __fdividef(2.f, 1.f + __expf(-2.f * x)) - 1.f;
}

__global__ void __cluster_dims__(8, 1, 1) __launch_bounds__(256, 1)
k2_lstm(const float* __restrict__ Whh, const float* __restrict__ Wih,
        const float* __restrict__ bih, const float* __restrict__ bhh,
        const float* __restrict__ h0,  const float* __restrict__ c0) {
    // hbuf[ph][p] = {b0[2p], b0[2p+1], b1[2p], b1[2p+1]}  (full H, both batches)
    __shared__ float4 hbuf[2][128];
    __shared__ float  psum[2][128][2];   // [khalf][local gate row][batch]
    __shared__ float  sq[2][T_STEPS];    // seq for the 2 batches
    __shared__ ull    mbar[2];

    const int tid = threadIdx.x;
    unsigned rank;
    asm("mov.u32 %0, %%cluster_ctarank;" : "=r"(rank));
    const int cid = blockIdx.x >> 3;
    const int b0g = cid * 2;

    const int l  = tid & 127;   // local gate row: gate = l>>5, unit = l&31
    const int kh = tid >> 7;    // k-half (0: k 0..127, 1: k 128..255)
    const int grow = (l >> 5) * HID + (int)rank * 32 + (l & 31);

    // ---- register-resident weights: 64 packed f32x2 (128 floats) -------------
    ull w[64];
    const ull* wrow = reinterpret_cast<const ull*>(Whh) + (size_t)grow * 128 + kh * 64;
#pragma unroll
    for (int j = 0; j < 64; j++) w[j] = wrow[j];

    const float bsum = bih[grow] + bhh[grow];
    const float wih  = Wih[grow];

    // ---- preload seq (both batches) ------------------------------------------
    for (int i = tid; i < 2 * T_STEPS; i += 256) {
        int bb = i >> 9, tt = i & 511;
        sq[bb][tt] = g_seq[tt * BATCH + b0g + bb];
    }
    // ---- fill hbuf[0] locally from h0 ----------------------------------------
    for (int i = tid; i < 2 * HID; i += 256) {
        int bb = i >> 8, U = i & 255;
        ((float*)&hbuf[0][U >> 1])[(U & 1) + 2 * bb] = h0[(b0g + bb) * HID + U];
    }
    // ---- updater state: threads 0..63 own (batch=tid>>5, unit=tid&31) --------
    const int ub = tid >> 5, uu = tid & 31;
    float creg = 0.f;
    if (tid < 64) creg = c0[(b0g + ub) * HID + (int)rank * 32 + uu];

    const unsigned hb_addr  = smem_u32(&hbuf[0][0]);
    const unsigned mb_addr0 = smem_u32(&mbar[0]);
    const unsigned mb_addr1 = smem_u32(&mbar[1]);
    if (tid == 0) {
        asm volatile("mbarrier.init.shared.b64 [%0], %1;" :: "r"(mb_addr0), "r"(8) : "memory");
        asm volatile("mbarrier.init.shared.b64 [%0], %1;" :: "r"(mb_addr1), "r"(8) : "memory");
    }
    __syncthreads();
    asm volatile("barrier.cluster.arrive.aligned;" ::: "memory");
    asm volatile("barrier.cluster.wait.aligned;"   ::: "memory");

    int par0 = 0, par1 = 0;

    // scatter target byte offset (within hbuf) for this updater thread
    const unsigned scat_off = (tid < 64)
        ? (unsigned)((((int)rank * 32 + uu) >> 1) * 16 +
                     (((((int)rank * 32 + uu) & 1)) + 2 * ub) * 4)
        : 0u;

    for (int t = 0; t < T_STEPS; t++) {
        const int ph = t & 1, nph = ph ^ 1;
        if (t > 0) {
            if (ph) { mbar_wait_acq(mb_addr1, par1); par1 ^= 1; }
            else    { mbar_wait_acq(mb_addr0, par0); par0 ^= 1; }
        }

        // ---- gate GEMV fragment: dot over this thread's 128-k half -----------
        const ulonglong2* hp =
            reinterpret_cast<const ulonglong2*>(&hbuf[ph][kh * 64]);
        ull a0 = 0ULL, a1 = 0ULL;
#pragma unroll
        for (int j = 0; j < 64; j++) {
            ulonglong2 h2 = hp[j];
            asm("fma.rn.f32x2 %0, %1, %2, %0;" : "+l"(a0) : "l"(w[j]), "l"(h2.x));
            asm("fma.rn.f32x2 %0, %1, %2, %0;" : "+l"(a1) : "l"(w[j]), "l"(h2.y));
        }
        float s0lo, s0hi, s1lo, s1hi;
        asm("mov.b64 {%0,%1}, %2;" : "=f"(s0lo), "=f"(s0hi) : "l"(a0));
        asm("mov.b64 {%0,%1}, %2;" : "=f"(s1lo), "=f"(s1hi) : "l"(a1));
        float s0 = s0lo + s0hi;
        float s1 = s1lo + s1hi;
        if (kh == 0) {
            s0 += bsum + wih * sq[0][t];
            s1 += bsum + wih * sq[1][t];
        }
        psum[kh][l][0] = s0;
        psum[kh][l][1] = s1;
        __syncthreads();

        // ---- state update (64 threads); PUSH h to all 8 CTAs ------------------
        if (tid < 64) {
            float gi = psum[0][uu][ub]      + psum[1][uu][ub];
            float gf = psum[0][32 + uu][ub] + psum[1][32 + uu][ub];
            float gg = psum[0][64 + uu][ub] + psum[1][64 + uu][ub];
            float go = psum[0][96 + uu][ub] + psum[1][96 + uu][ub];
            float ci = fsigmoid(gi);
            float cf = fsigmoid(gf);
            float co = fsigmoid(go);
            creg = cf * creg + ci * ftanh(gg);
            float hv = co * ftanh(creg);

            unsigned laddr = hb_addr + (unsigned)(nph * 2048) + scat_off;
#pragma unroll
            for (int r = 0; r < 8; r++) {
                unsigned raddr;
                asm("mapa.shared::cluster.u32 %0, %1, %2;" : "=r"(raddr) : "r"(laddr), "r"(r));
                asm volatile("st.shared::cluster.f32 [%0], %1;" :: "r"(raddr), "f"(hv) : "memory");
            }
            g_hs[((size_t)t * BATCH + b0g + ub) * HID + (int)rank * 32 + uu] = hv;
        }
        __syncthreads();

        // ---- signal: one arrive per peer CTA (8 threads) ----------------------
        if (tid < 8) {
            asm volatile("fence.acq_rel.cluster;" ::: "memory");
            unsigned target = ph ? mb_addr0 : mb_addr1;   // = mbar[nph]
            unsigned raddr;
            asm("mapa.shared::cluster.u32 %0, %1, %2;" : "=r"(raddr) : "r"(target), "r"(tid));
            asm volatile("mbarrier.arrive.release.cluster.shared::cluster.b64 _, [%0];"
                         :: "r"(raddr) : "memory");
        }
    }

    // keep smem alive until all peers' in-flight remote stores/arrives complete
    asm volatile("barrier.cluster.arrive.aligned;" ::: "memory");
    asm volatile("barrier.cluster.wait.aligned;"   ::: "memory");
}

// =============================================================================
// K3: AttLayer2 logits.  s2[t,b] = sum_a u2[a]*tanh( hs[t,b,:]@W2[:,a] + b2[a] )
// 128 CTAs: (b, t-quarter). 8x8 register tiles, f32x2.
// =============================================================================
__global__ __launch_bounds__(256) void k3_att2(const float* __restrict__ W2,
                                               const float* __restrict__ b2,
                                               const float* __restrict__ u2) {
    __shared__ float sh[128][33];   // [t-local][k]  (padded)
    __shared__ float sw[32][128];   // [k][a]
    __shared__ float sp[128][17];   // partial [t-local][tx]
    __shared__ float sb2[A2N], su2[A2N];

    const int tid = threadIdx.x;
    const int b = blockIdx.x & 31, tq = blockIdx.x >> 5;
    const int t0 = tq * 128;
    if (tid < A2N) { sb2[tid] = b2[tid]; su2[tid] = u2[tid]; }

    const int tx = tid & 15;   // a-group (8 a's each)
    const int ty = tid >> 4;   // t-group (8 t's each)

    ull acc[8][4];
#pragma unroll
    for (int i = 0; i < 8; i++)
#pragma unroll
        for (int p = 0; p < 4; p++) acc[i][p] = 0ULL;

    for (int kc = 0; kc < 8; kc++) {
        __syncthreads();
        for (int idx = tid; idx < 4096; idx += 256) {
            int tl = idx >> 5, k = idx & 31;
            sh[tl][k] = g_hs[((size_t)(t0 + tl) * BATCH + b) * HID + kc * 32 + k];
        }
        for (int idx = tid; idx < 4096; idx += 256) {
            int k = idx >> 7, a = idx & 127;
            sw[k][a] = W2[(kc * 32 + k) * A2N + a];
        }
        __syncthreads();
#pragma unroll 4
        for (int k = 0; k < 32; k++) {
            const ull* wv = reinterpret_cast<const ull*>(&sw[k][tx * 8]);
            ull w0 = wv[0], w1 = wv[1], w2_ = wv[2], w3 = wv[3];
#pragma unroll
            for (int i = 0; i < 8; i++) {
                float hvv = sh[ty * 8 + i][k];
                ull hh;
                asm("mov.b64 %0, {%1,%1};" : "=l"(hh) : "f"(hvv));
                asm("fma.rn.f32x2 %0, %1, %2, %0;" : "+l"(acc[i][0]) : "l"(w0),  "l"(hh));
                asm("fma.rn.f32x2 %0, %1, %2, %0;" : "+l"(acc[i][1]) : "l"(w1),  "l"(hh));
                asm("fma.rn.f32x2 %0, %1, %2, %0;" : "+l"(acc[i][2]) : "l"(w2_), "l"(hh));
                asm("fma.rn.f32x2 %0, %1, %2, %0;" : "+l"(acc[i][3]) : "l"(w3),  "l"(hh));
            }
        }
    }
    // epilogue: tanh + u2 dot over this thread's 8 a's
    float sres[8];
#pragma unroll
    for (int i = 0; i < 8; i++) sres[i] = 0.f;
#pragma unroll
    for (int i = 0; i < 8; i++) {
#pragma unroll
        for (int p = 0; p < 4; p++) {
            float lo, hi;
            asm("mov.b64 {%0,%1}, %2;" : "=f"(lo), "=f"(hi) : "l"(acc[i][p]));
            int a0 = tx * 8 + p * 2;
            sres[i] += su2[a0]     * tanhf(lo + sb2[a0]);
            sres[i] += su2[a0 + 1] * tanhf(hi + sb2[a0 + 1]);
        }
    }
#pragma unroll
    for (int i = 0; i < 8; i++) sp[ty * 8 + i][tx] = sres[i];
    __syncthreads();
    if (tid < 128) {
        float s = 0.f;
#pragma unroll
        for (int xx = 0; xx < 16; xx++) s += sp[tid][xx];
        g_s2[(t0 + tid) * BATCH + b] = s;
    }
}

// =============================================================================
// K4: softmax over T, attention pool, linear head.  One CTA per batch.
// =============================================================================
__global__ __launch_bounds__(256) void k4_final(const float* __restrict__ Wl,
                                                const float* __restrict__ bl,
                                                float* __restrict__ out) {
    __shared__ float a2s[T_STEPS];
    __shared__ float red[256];
    const int b = blockIdx.x, tid = threadIdx.x;

    for (int t = tid; t < T_STEPS; t += 256)
        a2s[t] = expf(g_s2[t * BATCH + b]);
    __syncthreads();

    float p = a2s[tid] + a2s[tid + 256];
    red[tid] = p;
    __syncthreads();
#pragma unroll
    for (int o = 128; o > 0; o >>= 1) {
        if (tid < o) red[tid] += red[tid + o];
        __syncthreads();
    }
    const float inv = 1.f / red[0];
    __syncthreads();

    // pooled[u] = sum_t a2[t] * hs[t][b][u]   (tid = u)
    float acc = 0.f;
    const float* hp = g_hs + (size_t)b * HID + tid;
#pragma unroll 8
    for (int t = 0; t < T_STEPS; t++)
        acc += a2s[t] * hp[(size_t)t * BATCH * HID];
    acc *= inv;

    float v = acc * Wl[tid];
    red[tid] = v;
    __syncthreads();
#pragma unroll
    for (int o = 128; o > 0; o >>= 1) {
        if (tid < o) red[tid] += red[tid + o];
        __syncthreads();
    }
    if (tid == 0) out[b] = red[0] + bl[0];
}

// =============================================================================
// launcher
// =============================================================================
extern "C" void kernel_launch(void* const* d_in, const int* in_sizes, int n_in,
                              void* d_out, int out_size) {
    const float* inputs = (const float*)d_in[0];
    const float* W1  = (const float*)d_in[1];
    const float* b1  = (const float*)d_in[2];
    const float* u1  = (const float*)d_in[3];
    const float* Wih = (const float*)d_in[4];
    const float* Whh = (const float*)d_in[5];
    const float* bih = (const float*)d_in[6];
    const float* bhh = (const float*)d_in[7];
    const float* h0  = (const float*)d_in[8];
    const float* c0  = (const float*)d_in[9];
    const float* W2  = (const float*)d_in[10];
    const float* b2  = (const float*)d_in[11];
    const float* u2  = (const float*)d_in[12];
    const float* Wl  = (const float*)d_in[13];
    const float* bl  = (const float*)d_in[14];
    float* out = (float*)d_out;

    k0_lut  <<<33, 256>>>(W1, b1, u1);
    k1_att1 <<<512, 256>>>(inputs);
    k_nop   <<<1, 32>>>();            // shifts ncu capture slot onto k2
    k2_lstm <<<128, 256>>>(Whh, Wih, bih, bhh, h0, c0);
    k3_att2 <<<128, 256>>>(W2, b2, u2);
    k4_final<<<32, 256>>>(Wl, bl, out);
}

// round 6
// speedup vs baseline: 1.6251x; 1.2015x over previous
#include <cuda_runtime.h>
#include <cstdint>

// Problem constants
#define T_STEPS 512
#define BATCH   32
#define DIM     512
#define HID     256
#define A1N     16
#define A2N     128

typedef unsigned long long ull;

// ---------------- device scratch (allocation-free rule: __device__ globals) ----
__device__ float g_lut[8200];                    // exp(f(x)) lookup table
__device__ float g_seq[T_STEPS * BATCH];         // stage-1 output (T,B)
__device__ float g_hs [T_STEPS * BATCH * HID];   // LSTM hidden history (T,B,H)
__device__ float g_s2 [T_STEPS * BATCH];         // stage-3 logits (T,B)

// =============================================================================
// K0: build LUT  g(x) = exp( sum_a u1[a] * tanh(x*W1[a] + b1[a]) ),  x in [-8,8]
// =============================================================================
__global__ void k0_lut(const float* __restrict__ W1,
                       const float* __restrict__ b1,
                       const float* __restrict__ u1) {
    int i = blockIdx.x * blockDim.x + threadIdx.x;
    if (i > 8192) return;
    float x = -8.f + (float)i * (16.f / 8192.f);
    float f = 0.f;
#pragma unroll
    for (int a = 0; a < A1N; a++)
        f += u1[a] * tanhf(x * W1[a] + b1[a]);
    g_lut[i] = expf(f);
}

// =============================================================================
// K1: AttLayer1 soft pool over D.  seq[t,b] = sum_d x*g(x) / sum_d g(x)
// =============================================================================
__global__ __launch_bounds__(256) void k1_att1(const float* __restrict__ x) {
    __shared__ float lut[8193];
    for (int i = threadIdx.x; i < 8193; i += 256) lut[i] = g_lut[i];
    __syncthreads();

    int warp = threadIdx.x >> 5, lane = threadIdx.x & 31;
#pragma unroll
    for (int q = 0; q < 4; q++) {
        int pair = blockIdx.x * 32 + warp * 4 + q;     // pair = t*B + b
        const float* xp = x + (size_t)pair * DIM;
        float aw = 0.f, axw = 0.f;
#pragma unroll 4
        for (int d = lane; d < DIM; d += 32) {
            float v = xp[d];
            float pos = (v + 8.f) * 512.f;
            pos = fminf(fmaxf(pos, 0.f), 8191.0f);
            int   i0 = (int)pos;
            float fr = pos - (float)i0;
            float g0 = lut[i0], g1 = lut[i0 + 1];
            float g  = g0 + fr * (g1 - g0);
            aw  += g;
            axw += v * g;
        }
#pragma unroll
        for (int o = 16; o > 0; o >>= 1) {
            aw  += __shfl_xor_sync(0xFFFFFFFFu, aw,  o);
            axw += __shfl_xor_sync(0xFFFFFFFFu, axw, o);
        }
        if (lane == 0) g_seq[pair] = axw / aw;
    }
}

// =============================================================================
// K_NOP: profiling-slot alignment dummy (keeps ncu capture slot on k2)
// =============================================================================
__global__ void k_nop() {}

// =============================================================================
// K2: LSTM recurrence.  8 clusters x 8 CTAs.  Cluster c owns batches 4c..4c+3,
// split into group A (4c, 4c+1) and group B (4c+2, 4c+3) processed alternately
// so each group's cross-CTA exchange latency hides under the other's compute.
// CTA rank r owns h-units [32r, 32r+32) -> 128 gate rows per group.
// Weights register-resident (128 regs, shared by both groups).
// Exchange: updaters PUSH h (st.shared::cluster) + flag (st.release.cluster);
// consumers spin on LOCAL flags with ld.acquire.
// =============================================================================
__device__ __forceinline__ unsigned smem_u32(const void* p) {
    unsigned a;
    asm("{ .reg .u64 t; cvta.to.shared.u64 t, %1; cvt.u32.u64 %0, t; }"
        : "=r"(a) : "l"(p));
    return a;
}

__device__ __forceinline__ unsigned ld_acq_shared(unsigned addr) {
    unsigned v;
    asm volatile("ld.acquire.cluster.shared::cta.u32 %0, [%1];"
                 : "=r"(v) : "r"(addr) : "memory");
    return v;
}

__device__ __forceinline__ float fsigmoid(float x) {
    return __fdividef(1.f, 1.f + __expf(-x));
}
__device__ __forceinline__ float ftanh(float x) {
    return __fdividef(2.f, 1.f + __expf(-2.f * x)) - 1.f;
}

// 128-k-half GEMV fragment with register weights; hp = &hbuf[ph][kh*64]
__device__ __forceinline__ void gemv128(const ulonglong2* hp, const ull* w,
                                        float& s0, float& s1) {
    ull a0 = 0ULL, a1 = 0ULL;
#pragma unroll
    for (int j = 0; j < 64; j++) {
        ulonglong2 h2 = hp[j];
        asm("fma.rn.f32x2 %0, %1, %2, %0;" : "+l"(a0) : "l"(w[j]), "l"(h2.x));
        asm("fma.rn.f32x2 %0, %1, %2, %0;" : "+l"(a1) : "l"(w[j]), "l"(h2.y));
    }
    float lo, hi;
    asm("mov.b64 {%0,%1}, %2;" : "=f"(lo), "=f"(hi) : "l"(a0));
    s0 = lo + hi;
    asm("mov.b64 {%0,%1}, %2;" : "=f"(lo), "=f"(hi) : "l"(a1));
    s1 = lo + hi;
}

__global__ void __cluster_dims__(8, 1, 1) __launch_bounds__(256, 1)
k2_lstm(const float* __restrict__ Whh, const float* __restrict__ Wih,
        const float* __restrict__ bih, const float* __restrict__ bhh,
        const float* __restrict__ h0,  const float* __restrict__ c0) {
    // per-group h buffers: [ph][p] = {b0[2p], b0[2p+1], b1[2p], b1[2p+1]}
    __shared__ float4 hbufA[2][128];
    __shared__ float4 hbufB[2][128];
    __shared__ float  psumA[2][128][2];
    __shared__ float  psumB[2][128][2];
    __shared__ float  sq[4][T_STEPS];          // seq for the 4 batches
    __shared__ __align__(16) unsigned flagsA[8], flagsB[8];

    const int tid = threadIdx.x;
    unsigned rank;
    asm("mov.u32 %0, %%cluster_ctarank;" : "=r"(rank));
    const int cid = blockIdx.x >> 3;
    const int b0g = cid * 4;

    const int l  = tid & 127;   // local gate row: gate = l>>5, unit = l&31
    const int kh = tid >> 7;    // k-half
    const int grow = (l >> 5) * HID + (int)rank * 32 + (l & 31);

    // ---- register-resident weights: 64 packed f32x2 (128 floats) -------------
    ull w[64];
    const ull* wrow = reinterpret_cast<const ull*>(Whh) + (size_t)grow * 128 + kh * 64;
#pragma unroll
    for (int j = 0; j < 64; j++) w[j] = wrow[j];

    const float bsum = bih[grow] + bhh[grow];
    const float wih  = Wih[grow];

    // ---- preload seq (4 batches) ----------------------------------------------
    for (int i = tid; i < 4 * T_STEPS; i += 256) {
        int bb = i >> 9, tt = i & 511;
        sq[bb][tt] = g_seq[tt * BATCH + b0g + bb];
    }
    // ---- fill hbufA[0]/hbufB[0] locally from h0 --------------------------------
    for (int i = tid; i < 2 * HID; i += 256) {
        int bb = i >> 8, U = i & 255;
        ((float*)&hbufA[0][U >> 1])[(U & 1) + 2 * bb] = h0[(b0g + bb) * HID + U];
        ((float*)&hbufB[0][U >> 1])[(U & 1) + 2 * bb] = h0[(b0g + 2 + bb) * HID + U];
    }
    if (tid < 8) { flagsA[tid] = 0; flagsB[tid] = 0; }

    // ---- updater state: threads 0..63 own (batch=tid>>5 in group, unit=tid&31)
    const int ub = tid >> 5, uu = tid & 31;
    float cregA = 0.f, cregB = 0.f;
    if (tid < 64) {
        cregA = c0[(b0g + ub) * HID + (int)rank * 32 + uu];
        cregB = c0[(b0g + 2 + ub) * HID + (int)rank * 32 + uu];
    }

    const unsigned hbA_addr = smem_u32(&hbufA[0][0]);
    const unsigned hbB_addr = smem_u32(&hbufB[0][0]);
    const unsigned flA_addr = smem_u32(&flagsA[0]);
    const unsigned flB_addr = smem_u32(&flagsB[0]);

    __syncthreads();
    asm volatile("barrier.cluster.arrive.aligned;" ::: "memory");
    asm volatile("barrier.cluster.wait.aligned;"   ::: "memory");

    // scatter byte offset within hbuf for this updater thread
    const unsigned scat_off = (tid < 64)
        ? (unsigned)((((int)rank * 32 + uu) >> 1) * 16 +
                     (((((int)rank * 32 + uu) & 1)) + 2 * ub) * 4)
        : 0u;

    for (int t = 0; t < T_STEPS; t++) {
        const int ph = t & 1, nph = ph ^ 1;
        const unsigned tgt = (unsigned)t;

        // ================= group A =================
        // spin until all 8 source CTAs have published h_t for group A
        for (;;) {
            bool ok = true;
#pragma unroll
            for (int i = 0; i < 8; i++)
                ok &= (ld_acq_shared(flA_addr + 4u * i) >= tgt);
            if (ok) break;
        }
        {
            const ulonglong2* hp = reinterpret_cast<const ulonglong2*>(&hbufA[ph][kh * 64]);
            float s0, s1;
            gemv128(hp, w, s0, s1);
            if (kh == 0) {
                s0 += bsum + wih * sq[0][t];
                s1 += bsum + wih * sq[1][t];
            }
            psumA[kh][l][0] = s0;
            psumA[kh][l][1] = s1;
        }
        __syncthreads();
        if (tid < 64) {
            float gi = psumA[0][uu][ub]      + psumA[1][uu][ub];
            float gf = psumA[0][32 + uu][ub] + psumA[1][32 + uu][ub];
            float gg = psumA[0][64 + uu][ub] + psumA[1][64 + uu][ub];
            float go = psumA[0][96 + uu][ub] + psumA[1][96 + uu][ub];
            float ci = fsigmoid(gi), cf = fsigmoid(gf), co = fsigmoid(go);
            cregA = cf * cregA + ci * ftanh(gg);
            float hv = co * ftanh(cregA);

            unsigned laddr = hbA_addr + (unsigned)(nph * 2048) + scat_off;
#pragma unroll
            for (int r = 0; r < 8; r++) {
                unsigned raddr;
                asm("mapa.shared::cluster.u32 %0, %1, %2;" : "=r"(raddr) : "r"(laddr), "r"(r));
                asm volatile("st.shared::cluster.f32 [%0], %1;" :: "r"(raddr), "f"(hv) : "memory");
            }
            g_hs[((size_t)t * BATCH + b0g + ub) * HID + (int)rank * 32 + uu] = hv;
            asm volatile("bar.sync 1, 64;" ::: "memory");
            if (tid < 8) {
                asm volatile("fence.acq_rel.cluster;" ::: "memory");
                unsigned lfl = flA_addr + 4u * rank;
                unsigned rfl;
                asm("mapa.shared::cluster.u32 %0, %1, %2;" : "=r"(rfl) : "r"(lfl), "r"(tid));
                asm volatile("st.release.cluster.shared::cluster.u32 [%0], %1;"
                             :: "r"(rfl), "r"((unsigned)(t + 1)) : "memory");
            }
        }

        // ================= group B =================
        for (;;) {
            bool ok = true;
#pragma unroll
            for (int i = 0; i < 8; i++)
                ok &= (ld_acq_shared(flB_addr + 4u * i) >= tgt);
            if (ok) break;
        }
        {
            const ulonglong2* hp = reinterpret_cast<const ulonglong2*>(&hbufB[ph][kh * 64]);
            float s0, s1;
            gemv128(hp, w, s0, s1);
            if (kh == 0) {
                s0 += bsum + wih * sq[2][t];
                s1 += bsum + wih * sq[3][t];
            }
            psumB[kh][l][0] = s0;
            psumB[kh][l][1] = s1;
        }
        __syncthreads();
        if (tid < 64) {
            float gi = psumB[0][uu][ub]      + psumB[1][uu][ub];
            float gf = psumB[0][32 + uu][ub] + psumB[1][32 + uu][ub];
            float gg = psumB[0][64 + uu][ub] + psumB[1][64 + uu][ub];
            float go = psumB[0][96 + uu][ub] + psumB[1][96 + uu][ub];
            float ci = fsigmoid(gi), cf = fsigmoid(gf), co = fsigmoid(go);
            cregB = cf * cregB + ci * ftanh(gg);
            float hv = co * ftanh(cregB);

            unsigned laddr = hbB_addr + (unsigned)(nph * 2048) + scat_off;
#pragma unroll
            for (int r = 0; r < 8; r++) {
                unsigned raddr;
                asm("mapa.shared::cluster.u32 %0, %1, %2;" : "=r"(raddr) : "r"(laddr), "r"(r));
                asm volatile("st.shared::cluster.f32 [%0], %1;" :: "r"(raddr), "f"(hv) : "memory");
            }
            g_hs[((size_t)t * BATCH + b0g + 2 + ub) * HID + (int)rank * 32 + uu] = hv;
            asm volatile("bar.sync 1, 64;" ::: "memory");
            if (tid < 8) {
                asm volatile("fence.acq_rel.cluster;" ::: "memory");
                unsigned lfl = flB_addr + 4u * rank;
                unsigned rfl;
                asm("mapa.shared::cluster.u32 %0, %1, %2;" : "=r"(rfl) : "r"(lfl), "r"(tid));
                asm volatile("st.release.cluster.shared::cluster.u32 [%0], %1;"
                             :: "r"(rfl), "r"((unsigned)(t + 1)) : "memory");
            }
        }
    }

    // keep smem alive until all peers' in-flight remote stores complete
    asm volatile("barrier.cluster.arrive.aligned;" ::: "memory");
    asm volatile("barrier.cluster.wait.aligned;"   ::: "memory");
}

// =============================================================================
// K3: AttLayer2 logits.  s2[t,b] = sum_a u2[a]*tanh( hs[t,b,:]@W2[:,a] + b2[a] )
// =============================================================================
__global__ __launch_bounds__(256) void k3_att2(const float* __restrict__ W2,
                                               const float* __restrict__ b2,
                                               const float* __restrict__ u2) {
    __shared__ float sh[128][33];
    __shared__ float sw[32][128];
    __shared__ float sp[128][17];
    __shared__ float sb2[A2N], su2[A2N];

    const int tid = threadIdx.x;
    const int b = blockIdx.x & 31, tq = blockIdx.x >> 5;
    const int t0 = tq * 128;
    if (tid < A2N) { sb2[tid] = b2[tid]; su2[tid] = u2[tid]; }

    const int tx = tid & 15;
    const int ty = tid >> 4;

    ull acc[8][4];
#pragma unroll
    for (int i = 0; i < 8; i++)
#pragma unroll
        for (int p = 0; p < 4; p++) acc[i][p] = 0ULL;

    for (int kc = 0; kc < 8; kc++) {
        __syncthreads();
        for (int idx = tid; idx < 4096; idx += 256) {
            int tl = idx >> 5, k = idx & 31;
            sh[tl][k] = g_hs[((size_t)(t0 + tl) * BATCH + b) * HID + kc * 32 + k];
        }
        for (int idx = tid; idx < 4096; idx += 256) {
            int k = idx >> 7, a = idx & 127;
            sw[k][a] = W2[(kc * 32 + k) * A2N + a];
        }
        __syncthreads();
#pragma unroll 4
        for (int k = 0; k < 32; k++) {
            const ull* wv = reinterpret_cast<const ull*>(&sw[k][tx * 8]);
            ull w0 = wv[0], w1 = wv[1], w2_ = wv[2], w3 = wv[3];
#pragma unroll
            for (int i = 0; i < 8; i++) {
                float hvv = sh[ty * 8 + i][k];
                ull hh;
                asm("mov.b64 %0, {%1,%1};" : "=l"(hh) : "f"(hvv));
                asm("fma.rn.f32x2 %0, %1, %2, %0;" : "+l"(acc[i][0]) : "l"(w0),  "l"(hh));
                asm("fma.rn.f32x2 %0, %1, %2, %0;" : "+l"(acc[i][1]) : "l"(w1),  "l"(hh));
                asm("fma.rn.f32x2 %0, %1, %2, %0;" : "+l"(acc[i][2]) : "l"(w2_), "l"(hh));
                asm("fma.rn.f32x2 %0, %1, %2, %0;" : "+l"(acc[i][3]) : "l"(w3),  "l"(hh));
            }
        }
    }
    float sres[8];
#pragma unroll
    for (int i = 0; i < 8; i++) sres[i] = 0.f;
#pragma unroll
    for (int i = 0; i < 8; i++) {
#pragma unroll
        for (int p = 0; p < 4; p++) {
            float lo, hi;
            asm("mov.b64 {%0,%1}, %2;" : "=f"(lo), "=f"(hi) : "l"(acc[i][p]));
            int a0 = tx * 8 + p * 2;
            sres[i] += su2[a0]     * tanhf(lo + sb2[a0]);
            sres[i] += su2[a0 + 1] * tanhf(hi + sb2[a0 + 1]);
        }
    }
#pragma unroll
    for (int i = 0; i < 8; i++) sp[ty * 8 + i][tx] = sres[i];
    __syncthreads();
    if (tid < 128) {
        float s = 0.f;
#pragma unroll
        for (int xx = 0; xx < 16; xx++) s += sp[tid][xx];
        g_s2[(t0 + tid) * BATCH + b] = s;
    }
}

// =============================================================================
// K4: softmax over T, attention pool, linear head.  One CTA per batch.
// =============================================================================
__global__ __launch_bounds__(256) void k4_final(const float* __restrict__ Wl,
                                                const float* __restrict__ bl,
                                                float* __restrict__ out) {
    __shared__ float a2s[T_STEPS];
    __shared__ float red[256];
    const int b = blockIdx.x, tid = threadIdx.x;

    for (int t = tid; t < T_STEPS; t += 256)
        a2s[t] = expf(g_s2[t * BATCH + b]);
    __syncthreads();

    float p = a2s[tid] + a2s[tid + 256];
    red[tid] = p;
    __syncthreads();
#pragma unroll
    for (int o = 128; o > 0; o >>= 1) {
        if (tid < o) red[tid] += red[tid + o];
        __syncthreads();
    }
    const float inv = 1.f / red[0];
    __syncthreads();

    float acc = 0.f;
    const float* hp = g_hs + (size_t)b * HID + tid;
#pragma unroll 8
    for (int t = 0; t < T_STEPS; t++)
        acc += a2s[t] * hp[(size_t)t * BATCH * HID];
    acc *= inv;

    float v = acc * Wl[tid];
    red[tid] = v;
    __syncthreads();
#pragma unroll
    for (int o = 128; o > 0; o >>= 1) {
        if (tid < o) red[tid] += red[tid + o];
        __syncthreads();
    }
    if (tid == 0) out[b] = red[0] + bl[0];
}

// =============================================================================
// launcher
// =============================================================================
extern "C" void kernel_launch(void* const* d_in, const int* in_sizes, int n_in,
                              void* d_out, int out_size) {
    const float* inputs = (const float*)d_in[0];
    const float* W1  = (const float*)d_in[1];
    const float* b1  = (const float*)d_in[2];
    const float* u1  = (const float*)d_in[3];
    const float* Wih = (const float*)d_in[4];
    const float* Whh = (const float*)d_in[5];
    const float* bih = (const float*)d_in[6];
    const float* bhh = (const float*)d_in[7];
    const float* h0  = (const float*)d_in[8];
    const float* c0  = (const float*)d_in[9];
    const float* W2  = (const float*)d_in[10];
    const float* b2  = (const float*)d_in[11];
    const float* u2  = (const float*)d_in[12];
    const float* Wl  = (const float*)d_in[13];
    const float* bl  = (const float*)d_in[14];
    float* out = (float*)d_out;

    k0_lut  <<<33, 256>>>(W1, b1, u1);
    k1_att1 <<<512, 256>>>(inputs);
    k_nop   <<<1, 32>>>();            // keeps ncu capture slot on k2
    k2_lstm <<<64, 256>>>(Whh, Wih, bih, bhh, h0, c0);
    k3_att2 <<<128, 256>>>(W2, b2, u2);
    k4_final<<<32, 256>>>(Wl, bl, out);
}